// round 3
// baseline (speedup 1.0000x reference)
#include <cuda_runtime.h>

#define N_NODES 50000
#define N_EDGES 600000
#define D 128
#define NLAYERS 5

typedef unsigned long long ull;

// ----------------- persistent device scratch -----------------
__device__ float g_h[N_NODES * D];      // layer-0 input embeddings
__device__ float g_z[N_NODES * D];      // z = h + agg
__device__ float g_out[N_NODES * D];    // MLP output (pre-BN)
__device__ float g_etab[9 * D];         // 9 distinct edge vectors
__device__ float g_stats[2 * D];        // column sum, sumsq
__device__ float g_aff[2 * D];          // per-feature scale, shift (BN folded)
__device__ int   g_deg[N_NODES];
__device__ int   g_off[N_NODES + 1];
__device__ int   g_cur[N_NODES];
__device__ int   g_csr[N_EDGES];        // src | (edge_code << 20)
__device__ int   g_is64;                // 1 if integer inputs are int64

// ----------------- f32x2 helpers (Blackwell packed FMA) -----------------
__device__ __forceinline__ ull splat2(float x) {
    ull r;
    asm("mov.b64 %0, {%1, %1};" : "=l"(r) : "f"(x));
    return r;
}
__device__ __forceinline__ void ffma2(ull& d, ull a, ull b) {
    asm("fma.rn.f32x2 %0, %1, %2, %0;" : "+l"(d) : "l"(a), "l"(b));
}
__device__ __forceinline__ void unpack2(ull v, float& lo, float& hi) {
    asm("mov.b64 {%0, %1}, %2;" : "=f"(lo), "=f"(hi) : "l"(v));
}

// logical integer index -> value, handling int32 or int64 (little-endian lo word)
__device__ __forceinline__ int getidx(const int* __restrict__ p, int i) {
    return g_is64 ? p[2 * i] : p[i];
}

// ----------------- dtype detection -----------------
__global__ void k_detect(const int* __restrict__ x) {
    if (threadIdx.x == 0) {
        int nz = 0;
        for (int i = 1; i < 128; i += 2) nz |= x[i];
        g_is64 = (nz == 0) ? 1 : 0;
    }
}

// ----------------- setup kernels -----------------
__global__ void k_embed(const int* __restrict__ x,
                        const float* __restrict__ elem,
                        const float* __restrict__ chir) {
    int i = blockIdx.x * blockDim.x + threadIdx.x;   // float4 slots
    if (i >= N_NODES * 32) return;
    int node = i >> 5, l = i & 31;
    int a = getidx(x, 2 * node);
    int c = getidx(x, 2 * node + 1);
    float4 va = __ldg((const float4*)(elem + a * D) + l);
    float4 vc = __ldg((const float4*)(chir + c * D) + l);
    float4 o = make_float4(va.x + vc.x, va.y + vc.y, va.z + vc.z, va.w + vc.w);
    ((float4*)(g_h + node * D))[l] = o;
}

__global__ void k_etab(const float* __restrict__ bt, const float* __restrict__ bd) {
    int code = blockIdx.x;          // 0..8
    int t = code / 3, d = code % 3;
    int c = threadIdx.x;
    g_etab[code * D + c] = bt[t * D + c] + bd[d * D + c];
}

__global__ void k_zero_deg() {
    int i = blockIdx.x * blockDim.x + threadIdx.x;
    if (i < N_NODES) g_deg[i] = 0;
}

__global__ void k_hist(const int* __restrict__ ei) {
    int e = blockIdx.x * blockDim.x + threadIdx.x;
    if (e < N_EDGES) {
        int dst = getidx(ei, N_EDGES + e);
        atomicAdd(&g_deg[dst], 1);
    }
}

__global__ void k_scan() {
    __shared__ int sh[1024];
    __shared__ int carry_s;
    int tid = threadIdx.x;
    if (tid == 0) carry_s = 0;
    __syncthreads();
    for (int base = 0; base < N_NODES; base += 1024) {
        int i = base + tid;
        int v = (i < N_NODES) ? g_deg[i] : 0;
        sh[tid] = v;
        __syncthreads();
        for (int off = 1; off < 1024; off <<= 1) {
            int t = (tid >= off) ? sh[tid - off] : 0;
            __syncthreads();
            sh[tid] += t;
            __syncthreads();
        }
        int incl = sh[tid];
        int c = carry_s;
        if (i < N_NODES) {
            g_off[i] = c + incl - v;
            g_cur[i] = c + incl - v;
        }
        __syncthreads();
        if (tid == 1023) carry_s = c + incl;
        __syncthreads();
    }
    if (tid == 0) g_off[N_NODES] = carry_s;
}

__global__ void k_fill(const int* __restrict__ ei, const int* __restrict__ ea) {
    int e = blockIdx.x * blockDim.x + threadIdx.x;
    if (e < N_EDGES) {
        int src = getidx(ei, e);
        int dst = getidx(ei, N_EDGES + e);
        int t = getidx(ea, 2 * e);
        int d = getidx(ea, 2 * e + 1);
        int pos = atomicAdd(&g_cur[dst], 1);
        g_csr[pos] = src | ((t * 3 + d) << 20);
    }
}

__global__ void k_zero_stats() {
    int i = threadIdx.x;
    if (i < 2 * D) g_stats[i] = 0.f;
}

// ----------------- aggregation: one warp per dst node -----------------
// input transform t(): layer 0 -> identity (reads g_h); layers>=1 ->
// relu(v*scale + shift) applied on the fly to prev layer's g_out.
__global__ void __launch_bounds__(256) k_agg(int layer) {
    __shared__ float et[9 * D];
    __shared__ float aff[2 * D];
    int tid = threadIdx.x;
    for (int i = tid; i < 9 * D; i += 256) et[i] = g_etab[i];
    if (tid < 2 * D) aff[tid] = g_aff[tid];
    __syncthreads();

    const int mode = (layer > 0);
    const float* __restrict__ in = mode ? g_out : g_h;

    int warp = tid >> 5, lane = tid & 31;
    int node = blockIdx.x * 8 + warp;
    if (node >= N_NODES) return;
    int c0 = lane * 4;

    float4 sc = make_float4(1.f, 1.f, 1.f, 1.f);
    float4 sf = make_float4(0.f, 0.f, 0.f, 0.f);
    if (mode) {
        sc = *(float4*)&aff[c0];
        sf = *(float4*)&aff[D + c0];
    }

    int beg = g_off[node], end = g_off[node + 1];
    float4 acc = make_float4(0.f, 0.f, 0.f, 0.f);

    for (int e0 = beg; e0 < end; e0 += 32) {
        int v = 0;
        if (e0 + lane < end) v = g_csr[e0 + lane];
        int cnt = min(32, end - e0);
        for (int j = 0; j < cnt; j++) {
            int vv = __shfl_sync(0xffffffffu, v, j);
            int src = vv & 0xFFFFF;
            int code = vv >> 20;
            float4 hv = __ldg((const float4*)(in + src * D) + lane);
            if (mode) {
                hv.x = fmaxf(fmaf(hv.x, sc.x, sf.x), 0.f);
                hv.y = fmaxf(fmaf(hv.y, sc.y, sf.y), 0.f);
                hv.z = fmaxf(fmaf(hv.z, sc.z, sf.z), 0.f);
                hv.w = fmaxf(fmaf(hv.w, sc.w, sf.w), 0.f);
            }
            const float* ep = et + code * D + c0;
            float4 ev = *(const float4*)ep;
            acc.x += fmaxf(hv.x + ev.x, 0.f);
            acc.y += fmaxf(hv.y + ev.y, 0.f);
            acc.z += fmaxf(hv.z + ev.z, 0.f);
            acc.w += fmaxf(hv.w + ev.w, 0.f);
        }
    }
    float4 hd = __ldg((const float4*)(in + node * D) + lane);
    if (mode) {
        hd.x = fmaxf(fmaf(hd.x, sc.x, sf.x), 0.f);
        hd.y = fmaxf(fmaf(hd.y, sc.y, sf.y), 0.f);
        hd.z = fmaxf(fmaf(hd.z, sc.z, sf.z), 0.f);
        hd.w = fmaxf(fmaf(hd.w, sc.w, sf.w), 0.f);
    }
    acc.x += hd.x; acc.y += hd.y; acc.z += hd.z; acc.w += hd.w;
    *(float4*)(g_z + node * D + c0) = acc;
}

// ----------------- fused MLP: out = relu(z@W1+b1)@W2+b2, + BN stats -----------
// 64 rows per block, 256 threads, f32x2 packed FMA, fp32 accuracy.
#define ZS_STRIDE 132
#define HS_STRIDE 260
#define SMEM_MLP (64 * ZS_STRIDE * 4 + 64 * HS_STRIDE * 4)

__global__ void __launch_bounds__(256, 2) k_mlp(const float* __restrict__ W1,
                                                const float* __restrict__ b1,
                                                const float* __restrict__ W2,
                                                const float* __restrict__ b2) {
    extern __shared__ float sm[];
    float* zs = sm;                        // [64][132]
    float* hs = sm + 64 * ZS_STRIDE;       // [64][260]
    const int tid = threadIdx.x;
    const int rowBase = blockIdx.x * 64;

    // stage z tile
    for (int i = tid; i < 64 * 32; i += 256) {
        int r = i >> 5, c4 = i & 31;
        int row = rowBase + r;
        float4 v = make_float4(0.f, 0.f, 0.f, 0.f);
        if (row < N_NODES) v = __ldg((const float4*)(g_z + row * D) + c4);
        *(float4*)(zs + r * ZS_STRIDE + c4 * 4) = v;
    }
    __syncthreads();

    const int cx = tid & 31;    // col group: 8 cols
    const int ry = tid >> 5;    // row group: 8 rows

    // Phase A: hidden[64][256] = relu(z @ W1 + b1)
    {
        ull acc[8][4];
        const float* bp0 = b1 + cx * 8;
#pragma unroll
        for (int p = 0; p < 4; p++) {
            ull bp = ((const ull*)bp0)[p];
#pragma unroll
            for (int r = 0; r < 8; r++) acc[r][p] = bp;
        }
        const float* zrow = zs + ry * 8 * ZS_STRIDE;
        const float* wp = W1 + cx * 8;
        for (int k = 0; k < D; k++) {
            ulonglong2 wa = *(const ulonglong2*)(wp + k * 256);
            ulonglong2 wb = *(const ulonglong2*)(wp + k * 256 + 4);
#pragma unroll
            for (int r = 0; r < 8; r++) {
                ull zz = splat2(zrow[r * ZS_STRIDE + k]);
                ffma2(acc[r][0], zz, wa.x);
                ffma2(acc[r][1], zz, wa.y);
                ffma2(acc[r][2], zz, wb.x);
                ffma2(acc[r][3], zz, wb.y);
            }
        }
#pragma unroll
        for (int r = 0; r < 8; r++) {
            float* hrow = hs + (ry * 8 + r) * HS_STRIDE + cx * 8;
#pragma unroll
            for (int p = 0; p < 4; p++) {
                float lo, hi;
                unpack2(acc[r][p], lo, hi);
                hrow[2 * p]     = fmaxf(lo, 0.f);
                hrow[2 * p + 1] = fmaxf(hi, 0.f);
            }
        }
    }
    __syncthreads();

    // Phase B: out[64][128] = hidden @ W2 + b2
    const int cx2 = tid & 31;   // 4 cols
    const int ry2 = tid >> 5;   // 8 rows
    float ov[8][4];
    {
        ull acc[8][2];
        const float* bp0 = b2 + cx2 * 4;
#pragma unroll
        for (int p = 0; p < 2; p++) {
            ull bp = ((const ull*)bp0)[p];
#pragma unroll
            for (int r = 0; r < 8; r++) acc[r][p] = bp;
        }
        const float* hrow0 = hs + ry2 * 8 * HS_STRIDE;
        const float* wp = W2 + cx2 * 4;
        for (int k = 0; k < 256; k++) {
            ulonglong2 w = *(const ulonglong2*)(wp + k * 128);
#pragma unroll
            for (int r = 0; r < 8; r++) {
                ull zz = splat2(hrow0[r * HS_STRIDE + k]);
                ffma2(acc[r][0], zz, w.x);
                ffma2(acc[r][1], zz, w.y);
            }
        }
#pragma unroll
        for (int r = 0; r < 8; r++) {
            unpack2(acc[r][0], ov[r][0], ov[r][1]);
            unpack2(acc[r][1], ov[r][2], ov[r][3]);
        }
    }

    // store + per-column partial stats
    float s[4] = {0.f, 0.f, 0.f, 0.f}, s2[4] = {0.f, 0.f, 0.f, 0.f};
#pragma unroll
    for (int r = 0; r < 8; r++) {
        int row = rowBase + ry2 * 8 + r;
        if (row < N_NODES) {
            float4 o = make_float4(ov[r][0], ov[r][1], ov[r][2], ov[r][3]);
            *(float4*)(g_out + row * D + cx2 * 4) = o;
#pragma unroll
            for (int j = 0; j < 4; j++) {
                s[j] += ov[r][j];
                s2[j] += ov[r][j] * ov[r][j];
            }
        }
    }
    __syncthreads();   // smem reuse for reduction
    float* red = sm;   // [8][128] sums, [8][128] sumsq
#pragma unroll
    for (int j = 0; j < 4; j++) {
        red[ry2 * 128 + cx2 * 4 + j] = s[j];
        red[1024 + ry2 * 128 + cx2 * 4 + j] = s2[j];
    }
    __syncthreads();
    if (tid < 128) {
        float ts = 0.f, ts2 = 0.f;
#pragma unroll
        for (int g = 0; g < 8; g++) {
            ts += red[g * 128 + tid];
            ts2 += red[1024 + g * 128 + tid];
        }
        atomicAdd(&g_stats[tid], ts);
        atomicAdd(&g_stats[128 + tid], ts2);
    }
}

// ----------------- BN finalize: fold to per-feature scale/shift -------------
__global__ void k_bn(const float* __restrict__ gamma, const float* __restrict__ beta) {
    int c = threadIdx.x;
    if (c < D) {
        const float invN = 1.0f / (float)N_NODES;
        float mean = g_stats[c] * invN;
        float var = g_stats[D + c] * invN - mean * mean;
        float rstd = rsqrtf(var + 1e-5f);
        float scl = rstd * gamma[c];
        g_aff[c] = scl;
        g_aff[D + c] = beta[c] - mean * scl;
    }
}

// ----------------- final: apply last BN (no relu) to d_out ------------------
__global__ void k_final(float* __restrict__ out) {
    int i = blockIdx.x * blockDim.x + threadIdx.x;   // float4 index
    if (i >= N_NODES * 32) return;
    int c0 = (i & 31) * 4;
    float4 v = ((const float4*)g_out)[i];
    float4 sc = *(const float4*)&g_aff[c0];
    float4 sf = *(const float4*)&g_aff[D + c0];
    v.x = fmaf(v.x, sc.x, sf.x);
    v.y = fmaf(v.y, sc.y, sf.y);
    v.z = fmaf(v.z, sc.z, sf.z);
    v.w = fmaf(v.w, sc.w, sf.w);
    ((float4*)out)[i] = v;
}

// ----------------- launch -----------------
extern "C" void kernel_launch(void* const* d_in, const int* in_sizes, int n_in,
                              void* d_out, int out_size) {
    const int*   x    = (const int*)d_in[0];
    const int*   ei   = (const int*)d_in[1];
    const int*   ea   = (const int*)d_in[2];
    const float* elem = (const float*)d_in[3];
    const float* chir = (const float*)d_in[4];
    const float* bt   = (const float*)d_in[5];
    const float* bd   = (const float*)d_in[6];
    const float* W1   = (const float*)d_in[7];
    const float* b1   = (const float*)d_in[8];
    const float* W2   = (const float*)d_in[9];
    const float* b2   = (const float*)d_in[10];
    const float* bng  = (const float*)d_in[11];
    const float* bnb  = (const float*)d_in[12];
    float* out = (float*)d_out;

    cudaFuncSetAttribute(k_mlp, cudaFuncAttributeMaxDynamicSharedMemorySize, SMEM_MLP);

    k_detect<<<1, 32>>>(x);
    k_embed<<<(N_NODES * 32 + 255) / 256, 256>>>(x, elem, chir);
    k_etab<<<9, 128>>>(bt, bd);
    k_zero_deg<<<(N_NODES + 255) / 256, 256>>>();
    k_hist<<<(N_EDGES + 255) / 256, 256>>>(ei);
    k_scan<<<1, 1024>>>();
    k_fill<<<(N_EDGES + 255) / 256, 256>>>(ei, ea);

    const int mlp_blocks = (N_NODES + 63) / 64;
    for (int l = 0; l < NLAYERS; l++) {
        k_zero_stats<<<1, 256>>>();
        k_agg<<<(N_NODES + 7) / 8, 256>>>(l);
        k_mlp<<<mlp_blocks, 256, SMEM_MLP>>>(W1, b1, W2, b2);
        k_bn<<<1, 128>>>(bng + l * D, bnb + l * D);
    }
    k_final<<<(N_NODES * 32 + 255) / 256, 256>>>(out);
}

// round 6
// speedup vs baseline: 1.2572x; 1.2572x over previous
#include <cuda_runtime.h>

#define N_NODES 50000
#define N_EDGES 600000
#define D 128
#define NLAYERS 5
#define NT 391                    // ceil(50000/128) row tiles of 128

typedef unsigned long long ull;
typedef unsigned int u32;

// ----------------- persistent device scratch -----------------
__device__ float g_h[N_NODES * D];
__device__ float g_z[NT * 128 * D];
__device__ float g_out[N_NODES * D];
__device__ float g_etab[9 * D];
__device__ float g_stats[2 * D];
__device__ float g_aff[2 * D];
__device__ int   g_deg[N_NODES];
__device__ int   g_off[N_NODES + 1];
__device__ int   g_cur[N_NODES];
__device__ int   g_csr[N_EDGES];
__device__ int   g_is64;
__device__ int   g_cnt;
// hidden activations per tile: hi plane [128][256] bf16 (65536B) + lo plane
__device__ __align__(16) unsigned char g_hid[(size_t)NT * 131072];
// weight images: [n][k] bf16, hi plane then lo plane (65536B each)
__device__ __align__(16) unsigned char g_w1T[131072];   // n=256, k=128
__device__ __align__(16) unsigned char g_w2T[131072];   // n=128, k=256

// ----------------- helpers -----------------
__device__ __forceinline__ u32 smem_u32(const void* p) {
    u32 a;
    asm("{ .reg .u64 t; cvta.to.shared.u64 t, %1; cvt.u32.u64 %0, t; }" : "=r"(a) : "l"(p));
    return a;
}
// split two floats into hi-pair / lo-pair bf16x2 words (x0 -> low half)
__device__ __forceinline__ void split2(float x0, float x1, u32& hp, u32& lp) {
    asm("cvt.rn.bf16x2.f32 %0, %1, %2;" : "=r"(hp) : "f"(x1), "f"(x0));
    float h0 = __uint_as_float(hp << 16);
    float h1 = __uint_as_float(hp & 0xffff0000u);
    float r0 = x0 - h0, r1 = x1 - h1;
    asm("cvt.rn.bf16x2.f32 %0, %1, %2;" : "=r"(lp) : "f"(r1), "f"(r0));
}
__device__ __forceinline__ void ldsm4(u32 addr, u32& r0, u32& r1, u32& r2, u32& r3) {
    asm volatile("ldmatrix.sync.aligned.m8n8.x4.shared.b16 {%0,%1,%2,%3}, [%4];"
                 : "=r"(r0), "=r"(r1), "=r"(r2), "=r"(r3) : "r"(addr));
}
__device__ __forceinline__ void mma16816(float* c, u32 a0, u32 a1, u32 a2, u32 a3,
                                         u32 b0, u32 b1) {
    asm volatile(
        "mma.sync.aligned.m16n8k16.row.col.f32.bf16.bf16.f32 "
        "{%0,%1,%2,%3}, {%4,%5,%6,%7}, {%8,%9}, {%0,%1,%2,%3};"
        : "+f"(c[0]), "+f"(c[1]), "+f"(c[2]), "+f"(c[3])
        : "r"(a0), "r"(a1), "r"(a2), "r"(a3), "r"(b0), "r"(b1));
}

__device__ __forceinline__ int getidx(const int* __restrict__ p, int i) {
    return g_is64 ? p[2 * i] : p[i];
}

// ----------------- setup -----------------
__global__ void k_detect(const int* __restrict__ x) {
    if (threadIdx.x == 0) {
        int nz = 0;
        for (int i = 1; i < 128; i += 2) nz |= x[i];
        g_is64 = (nz == 0) ? 1 : 0;
    }
}

__global__ void k_embed(const int* __restrict__ x,
                        const float* __restrict__ elem,
                        const float* __restrict__ chir) {
    int i = blockIdx.x * blockDim.x + threadIdx.x;
    if (i >= N_NODES * 32) return;
    int node = i >> 5, l = i & 31;
    int a = getidx(x, 2 * node);
    int c = getidx(x, 2 * node + 1);
    float4 va = __ldg((const float4*)(elem + a * D) + l);
    float4 vc = __ldg((const float4*)(chir + c * D) + l);
    ((float4*)(g_h + node * D))[l] =
        make_float4(va.x + vc.x, va.y + vc.y, va.z + vc.z, va.w + vc.w);
}

__global__ void k_etab(const float* __restrict__ bt, const float* __restrict__ bd) {
    int code = blockIdx.x, t = code / 3, d = code % 3, c = threadIdx.x;
    g_etab[code * D + c] = bt[t * D + c] + bd[d * D + c];
}

__global__ void k_zero_deg() {
    int i = blockIdx.x * blockDim.x + threadIdx.x;
    if (i < N_NODES) g_deg[i] = 0;
    if (blockIdx.x == 0) {
        if (threadIdx.x < 256) g_stats[threadIdx.x] = 0.f;
        if (threadIdx.x == 0) g_cnt = 0;
    }
}

__global__ void k_hist(const int* __restrict__ ei) {
    int e = blockIdx.x * blockDim.x + threadIdx.x;
    if (e < N_EDGES) atomicAdd(&g_deg[getidx(ei, N_EDGES + e)], 1);
}

__global__ void k_scan() {
    __shared__ int sh[1024];
    __shared__ int carry_s;
    int tid = threadIdx.x;
    if (tid == 0) carry_s = 0;
    __syncthreads();
    for (int base = 0; base < N_NODES; base += 1024) {
        int i = base + tid;
        int v = (i < N_NODES) ? g_deg[i] : 0;
        sh[tid] = v;
        __syncthreads();
        for (int off = 1; off < 1024; off <<= 1) {
            int t = (tid >= off) ? sh[tid - off] : 0;
            __syncthreads();
            sh[tid] += t;
            __syncthreads();
        }
        int incl = sh[tid];
        int c = carry_s;
        if (i < N_NODES) { g_off[i] = c + incl - v; g_cur[i] = c + incl - v; }
        __syncthreads();
        if (tid == 1023) carry_s = c + incl;
        __syncthreads();
    }
    if (tid == 0) g_off[N_NODES] = carry_s;
}

__global__ void k_fill(const int* __restrict__ ei, const int* __restrict__ ea) {
    int e = blockIdx.x * blockDim.x + threadIdx.x;
    if (e < N_EDGES) {
        int src = getidx(ei, e);
        int dst = getidx(ei, N_EDGES + e);
        int t = getidx(ea, 2 * e);
        int d = getidx(ea, 2 * e + 1);
        int pos = atomicAdd(&g_cur[dst], 1);
        g_csr[pos] = src | ((t * 3 + d) << 20);
    }
}

// weight images: B[n][k] = W[k][n], split bf16 hi/lo planes
__global__ void k_prep(const float* __restrict__ W1, const float* __restrict__ W2) {
    int idx = blockIdx.x * blockDim.x + threadIdx.x;
    if (idx < 16384) {                        // W1: n 0..255, k pairs 0..63
        int n = idx >> 6, kp = idx & 63, k = kp * 2;
        float a = __ldg(W1 + k * 256 + n);
        float b = __ldg(W1 + (k + 1) * 256 + n);
        u32 hp, lp; split2(a, b, hp, lp);
        ((u32*)g_w1T)[n * 64 + kp] = hp;
        ((u32*)g_w1T)[16384 + n * 64 + kp] = lp;
    } else if (idx < 32768) {                 // W2: n 0..127, k pairs 0..127
        int q = idx - 16384;
        int n = q >> 7, kp = q & 127, k = kp * 2;
        float a = __ldg(W2 + k * 128 + n);
        float b = __ldg(W2 + (k + 1) * 128 + n);
        u32 hp, lp; split2(a, b, hp, lp);
        ((u32*)g_w2T)[n * 128 + kp] = hp;
        ((u32*)g_w2T)[16384 + n * 128 + kp] = lp;
    }
}

// ----------------- aggregation: one warp per dst node -----------------
__global__ void __launch_bounds__(256) k_agg(int layer) {
    __shared__ float et[9 * D];
    __shared__ float aff[2 * D];
    int tid = threadIdx.x;
    for (int i = tid; i < 9 * D; i += 256) et[i] = g_etab[i];
    if (tid < 2 * D) aff[tid] = g_aff[tid];
    __syncthreads();

    const int mode = (layer > 0);
    const float* __restrict__ in = mode ? g_out : g_h;

    int warp = tid >> 5, lane = tid & 31;
    int node = blockIdx.x * 8 + warp;
    if (node >= N_NODES) return;
    int c0 = lane * 4;

    float4 sc = make_float4(1.f, 1.f, 1.f, 1.f);
    float4 sf = make_float4(0.f, 0.f, 0.f, 0.f);
    if (mode) { sc = *(float4*)&aff[c0]; sf = *(float4*)&aff[D + c0]; }

    int beg = g_off[node], end = g_off[node + 1];
    float4 acc = make_float4(0.f, 0.f, 0.f, 0.f);

    for (int e0 = beg; e0 < end; e0 += 32) {
        int v = 0;
        if (e0 + lane < end) v = g_csr[e0 + lane];
        int cnt = min(32, end - e0);
        for (int j = 0; j < cnt; j++) {
            int vv = __shfl_sync(0xffffffffu, v, j);
            int src = vv & 0xFFFFF;
            int code = vv >> 20;
            float4 hv = __ldg((const float4*)(in + src * D) + lane);
            if (mode) {
                hv.x = fmaxf(fmaf(hv.x, sc.x, sf.x), 0.f);
                hv.y = fmaxf(fmaf(hv.y, sc.y, sf.y), 0.f);
                hv.z = fmaxf(fmaf(hv.z, sc.z, sf.z), 0.f);
                hv.w = fmaxf(fmaf(hv.w, sc.w, sf.w), 0.f);
            }
            float4 ev = *(const float4*)(et + code * D + c0);
            acc.x += fmaxf(hv.x + ev.x, 0.f);
            acc.y += fmaxf(hv.y + ev.y, 0.f);
            acc.z += fmaxf(hv.z + ev.z, 0.f);
            acc.w += fmaxf(hv.w + ev.w, 0.f);
        }
    }
    float4 hd = __ldg((const float4*)(in + node * D) + lane);
    if (mode) {
        hd.x = fmaxf(fmaf(hd.x, sc.x, sf.x), 0.f);
        hd.y = fmaxf(fmaf(hd.y, sc.y, sf.y), 0.f);
        hd.z = fmaxf(fmaf(hd.z, sc.z, sf.z), 0.f);
        hd.w = fmaxf(fmaf(hd.w, sc.w, sf.w), 0.f);
    }
    acc.x += hd.x; acc.y += hd.y; acc.z += hd.z; acc.w += hd.w;
    *(float4*)(g_z + node * D + c0) = acc;
}

// ----------------- GEMM1: hidden = relu(z@W1+b1) -> split-bf16 planes -------
// smem: B hi/lo [256][272B], A hi/lo [128][272B], bias[256]
#define KA_B_HI 0
#define KA_B_LO 69632
#define KA_A_HI 139264
#define KA_A_LO 174080
#define KA_BIAS 208896
#define KA_SMEM 209920

__global__ void __launch_bounds__(256, 1) kA(const float* __restrict__ b1) {
    extern __shared__ char sm[];
    u32 sb = smem_u32(sm);
    const int tid = threadIdx.x;
    const int warp = tid >> 5, lane = tid & 31;

    // stage weights (once) + bias
    {
        const uint4* src = (const uint4*)g_w1T;
        for (int i = tid; i < 8192; i += 256) {
            int p = i >> 12, r = (i >> 4) & 255, w = i & 15;
            *(uint4*)(sm + KA_B_HI + p * 69632 + r * 272 + w * 16) =
                src[p * 4096 + r * 16 + w];
        }
        ((float*)(sm + KA_BIAS))[tid] = __ldg(b1 + tid);
    }
    __syncthreads();

    const int wr = warp >> 2, wc = warp & 3;        // 2 x 4 warp grid, 64x64 tiles
    const u32 aHi = sb + KA_A_HI + (wr * 64 + (lane & 15)) * 272 + (lane >> 4) * 16;
    const u32 aLo = aHi + (KA_A_LO - KA_A_HI);
    const u32 bHi = sb + KA_B_HI + (wc * 64 + (lane & 15)) * 272 + (lane >> 4) * 16;
    const u32 bLo = bHi + 69632;
    const float* bias = (const float*)(sm + KA_BIAS);

    for (int tile = blockIdx.x; tile < NT; tile += gridDim.x) {
        // stage A: z fp32 -> split bf16 hi/lo
        for (int i = tid; i < 4096; i += 256) {
            int r = i >> 5, c4 = i & 31;
            int row = tile * 128 + r;
            float4 v = make_float4(0.f, 0.f, 0.f, 0.f);
            if (row < N_NODES) v = __ldg((const float4*)(g_z + (size_t)row * D) + c4);
            u32 h0, l0, h1, l1;
            split2(v.x, v.y, h0, l0);
            split2(v.z, v.w, h1, l1);
            *(ull*)(sm + KA_A_HI + r * 272 + c4 * 8) = (ull)h0 | ((ull)h1 << 32);
            *(ull*)(sm + KA_A_LO + r * 272 + c4 * 8) = (ull)l0 | ((ull)l1 << 32);
        }
        __syncthreads();

        float acc[4][8][4];
#pragma unroll
        for (int a = 0; a < 4; a++)
#pragma unroll
            for (int b = 0; b < 8; b++)
#pragma unroll
                for (int c = 0; c < 4; c++) acc[a][b][c] = 0.f;

        for (int ks = 0; ks < 8; ks++) {
            const u32 ko = ks * 32;
            u32 ah[4][4], al[4][4];
#pragma unroll
            for (int mt = 0; mt < 4; mt++) {
                ldsm4(aHi + mt * (16 * 272) + ko, ah[mt][0], ah[mt][1], ah[mt][2], ah[mt][3]);
                ldsm4(aLo + mt * (16 * 272) + ko, al[mt][0], al[mt][1], al[mt][2], al[mt][3]);
            }
#pragma unroll
            for (int g = 0; g < 4; g++) {
                u32 bh0, bh1, bh2, bh3, bl0, bl1, bl2, bl3;
                ldsm4(bHi + g * (16 * 272) + ko, bh0, bh1, bh2, bh3);
                ldsm4(bLo + g * (16 * 272) + ko, bl0, bl1, bl2, bl3);
#pragma unroll
                for (int mt = 0; mt < 4; mt++) {
                    mma16816(acc[mt][2 * g],     ah[mt][0], ah[mt][1], ah[mt][2], ah[mt][3], bh0, bh2);
                    mma16816(acc[mt][2 * g + 1], ah[mt][0], ah[mt][1], ah[mt][2], ah[mt][3], bh1, bh3);
                    mma16816(acc[mt][2 * g],     ah[mt][0], ah[mt][1], ah[mt][2], ah[mt][3], bl0, bl2);
                    mma16816(acc[mt][2 * g + 1], ah[mt][0], ah[mt][1], ah[mt][2], ah[mt][3], bl1, bl3);
                    mma16816(acc[mt][2 * g],     al[mt][0], al[mt][1], al[mt][2], al[mt][3], bh0, bh2);
                    mma16816(acc[mt][2 * g + 1], al[mt][0], al[mt][1], al[mt][2], al[mt][3], bh1, bh3);
                }
            }
        }

        // epilogue: bias + relu + re-split -> g_hid planes
        u32* hidHi = (u32*)(g_hid + (size_t)tile * 131072);
        u32* hidLo = hidHi + 16384;
        const int m0 = wr * 64, n0 = wc * 64;
#pragma unroll
        for (int mt = 0; mt < 4; mt++)
#pragma unroll
            for (int nt = 0; nt < 8; nt++) {
                int col = n0 + nt * 8 + 2 * (lane & 3);
                int r0 = m0 + mt * 16 + (lane >> 2);
                float bv0 = bias[col], bv1 = bias[col + 1];
                u32 hp, lp;
                float v0 = fmaxf(acc[mt][nt][0] + bv0, 0.f);
                float v1 = fmaxf(acc[mt][nt][1] + bv1, 0.f);
                split2(v0, v1, hp, lp);
                hidHi[r0 * 128 + (col >> 1)] = hp;
                hidLo[r0 * 128 + (col >> 1)] = lp;
                v0 = fmaxf(acc[mt][nt][2] + bv0, 0.f);
                v1 = fmaxf(acc[mt][nt][3] + bv1, 0.f);
                split2(v0, v1, hp, lp);
                hidHi[(r0 + 8) * 128 + (col >> 1)] = hp;
                hidLo[(r0 + 8) * 128 + (col >> 1)] = lp;
            }
        __syncthreads();
    }
}

// ----------------- GEMM2: g_out = hidden @ W2 + b2 --------------------------
// smem: B hi/lo [128][528B], A hi/lo [128][272B] (half-K staged), bias[128]
#define KB_B_HI 0
#define KB_B_LO 67584
#define KB_A_HI 135168
#define KB_A_LO 169984
#define KB_BIAS 204800
#define KB_SMEM 205312

__global__ void __launch_bounds__(256, 1) kB(const float* __restrict__ b2) {
    extern __shared__ char sm[];
    u32 sb = smem_u32(sm);
    const int tid = threadIdx.x;
    const int warp = tid >> 5, lane = tid & 31;

    {
        const uint4* src = (const uint4*)g_w2T;
        for (int i = tid; i < 8192; i += 256) {
            int p = i >> 12, r = (i >> 5) & 127, w = i & 31;
            *(uint4*)(sm + KB_B_HI + p * 67584 + r * 528 + w * 16) =
                src[p * 4096 + r * 32 + w];
        }
        if (tid < 128) ((float*)(sm + KB_BIAS))[tid] = __ldg(b2 + tid);
    }
    __syncthreads();

    const int wr = warp >> 2, wc = warp & 3;        // 2 x 4 grid, 64x32 tiles
    const u32 aHi = sb + KB_A_HI + (wr * 64 + (lane & 15)) * 272 + (lane >> 4) * 16;
    const u32 aLo = aHi + (KB_A_LO - KB_A_HI);
    const u32 bHi = sb + KB_B_HI + (wc * 32 + (lane & 15)) * 528 + (lane >> 4) * 16;
    const u32 bLo = bHi + 67584;
    const float* bias = (const float*)(sm + KB_BIAS);

    for (int tile = blockIdx.x; tile < NT; tile += gridDim.x) {
        float acc[4][4][4];
#pragma unroll
        for (int a = 0; a < 4; a++)
#pragma unroll
            for (int b = 0; b < 4; b++)
#pragma unroll
                for (int c = 0; c < 4; c++) acc[a][b][c] = 0.f;

        for (int pass = 0; pass < 2; pass++) {
            // stage A half-K: linear copy from g_hid planes into padded smem
            for (int i = tid; i < 4096; i += 256) {
                int p = i >> 11, r = (i >> 4) & 127, w = i & 15;
                *(uint4*)(sm + KB_A_HI + p * 34816 + r * 272 + w * 16) =
                    ((const uint4*)(g_hid + (size_t)tile * 131072 + p * 65536))
                        [r * 32 + pass * 16 + w];
            }
            __syncthreads();

            for (int ks = 0; ks < 8; ks++) {
                const u32 ko = ks * 32;
                const u32 bo = pass * 256 + ko;
                u32 ah[4][4], al[4][4];
#pragma unroll
                for (int mt = 0; mt < 4; mt++) {
                    ldsm4(aHi + mt * (16 * 272) + ko, ah[mt][0], ah[mt][1], ah[mt][2], ah[mt][3]);
                    ldsm4(aLo + mt * (16 * 272) + ko, al[mt][0], al[mt][1], al[mt][2], al[mt][3]);
                }
#pragma unroll
                for (int g = 0; g < 2; g++) {
                    u32 bh0, bh1, bh2, bh3, bl0, bl1, bl2, bl3;
                    ldsm4(bHi + g * (16 * 528) + bo, bh0, bh1, bh2, bh3);
                    ldsm4(bLo + g * (16 * 528) + bo, bl0, bl1, bl2, bl3);
#pragma unroll
                    for (int mt = 0; mt < 4; mt++) {
                        mma16816(acc[mt][2 * g],     ah[mt][0], ah[mt][1], ah[mt][2], ah[mt][3], bh0, bh2);
                        mma16816(acc[mt][2 * g + 1], ah[mt][0], ah[mt][1], ah[mt][2], ah[mt][3], bh1, bh3);
                        mma16816(acc[mt][2 * g],     ah[mt][0], ah[mt][1], ah[mt][2], ah[mt][3], bl0, bl2);
                        mma16816(acc[mt][2 * g + 1], ah[mt][0], ah[mt][1], ah[mt][2], ah[mt][3], bl1, bl3);
                        mma16816(acc[mt][2 * g],     al[mt][0], al[mt][1], al[mt][2], al[mt][3], bh0, bh2);
                        mma16816(acc[mt][2 * g + 1], al[mt][0], al[mt][1], al[mt][2], al[mt][3], bh1, bh3);
                    }
                }
            }
            __syncthreads();
        }

        // epilogue: bias, write fp32 g_out
        const int m0 = wr * 64, n0 = wc * 32;
#pragma unroll
        for (int mt = 0; mt < 4; mt++)
#pragma unroll
            for (int nt = 0; nt < 4; nt++) {
                int col = n0 + nt * 8 + 2 * (lane & 3);
                int r0 = tile * 128 + m0 + mt * 16 + (lane >> 2);
                float bv0 = bias[col], bv1 = bias[col + 1];
                if (r0 < N_NODES) {
                    float2 o = make_float2(acc[mt][nt][0] + bv0, acc[mt][nt][1] + bv1);
                    *(float2*)(g_out + (size_t)r0 * D + col) = o;
                }
                if (r0 + 8 < N_NODES) {
                    float2 o = make_float2(acc[mt][nt][2] + bv0, acc[mt][nt][3] + bv1);
                    *(float2*)(g_out + (size_t)(r0 + 8) * D + col) = o;
                }
            }
    }
}

// ----------------- BN stats + fold (self-resetting, last-block fold) --------
__global__ void k_stats(const float* __restrict__ gamma, const float* __restrict__ beta) {
    __shared__ float red[2][2][128];
    __shared__ int isLast;
    int tid = threadIdx.x;
    int col = tid & 127, half = tid >> 7;
    int rowBase = blockIdx.x * 128;
    float s = 0.f, s2 = 0.f;
    for (int r = half; r < 128; r += 2) {
        int row = rowBase + r;
        if (row < N_NODES) {
            float v = g_out[(size_t)row * D + col];
            s += v; s2 += v * v;
        }
    }
    red[half][0][col] = s;
    red[half][1][col] = s2;
    __syncthreads();
    if (tid < 128) {
        atomicAdd(&g_stats[col],       red[0][0][col] + red[1][0][col]);
        atomicAdd(&g_stats[128 + col], red[0][1][col] + red[1][1][col]);
    }
    __syncthreads();
    if (tid == 0) {
        __threadfence();
        int old = atomicAdd(&g_cnt, 1);
        isLast = (old == (int)gridDim.x - 1);
    }
    __syncthreads();
    if (isLast) {
        if (tid < 128) {
            float sum  = atomicAdd(&g_stats[tid], 0.f);
            float sum2 = atomicAdd(&g_stats[128 + tid], 0.f);
            const float invN = 1.0f / (float)N_NODES;
            float mean = sum * invN;
            float var = sum2 * invN - mean * mean;
            float scl = rsqrtf(var + 1e-5f) * __ldg(gamma + tid);
            g_aff[tid] = scl;
            g_aff[128 + tid] = __ldg(beta + tid) - mean * scl;
            g_stats[tid] = 0.f;
            g_stats[128 + tid] = 0.f;
        }
        if (tid == 0) g_cnt = 0;
    }
}

// ----------------- final: apply last BN (no relu) -> d_out ------------------
__global__ void k_final(float* __restrict__ out) {
    int i = blockIdx.x * blockDim.x + threadIdx.x;
    if (i >= N_NODES * 32) return;
    int c0 = (i & 31) * 4;
    float4 v = ((const float4*)g_out)[i];
    float4 sc = *(const float4*)&g_aff[c0];
    float4 sf = *(const float4*)&g_aff[D + c0];
    v.x = fmaf(v.x, sc.x, sf.x);
    v.y = fmaf(v.y, sc.y, sf.y);
    v.z = fmaf(v.z, sc.z, sf.z);
    v.w = fmaf(v.w, sc.w, sf.w);
    ((float4*)out)[i] = v;
}

// ----------------- launch -----------------
extern "C" void kernel_launch(void* const* d_in, const int* in_sizes, int n_in,
                              void* d_out, int out_size) {
    const int*   x    = (const int*)d_in[0];
    const int*   ei   = (const int*)d_in[1];
    const int*   ea   = (const int*)d_in[2];
    const float* elem = (const float*)d_in[3];
    const float* chir = (const float*)d_in[4];
    const float* bt   = (const float*)d_in[5];
    const float* bd   = (const float*)d_in[6];
    const float* W1   = (const float*)d_in[7];
    const float* b1   = (const float*)d_in[8];
    const float* W2   = (const float*)d_in[9];
    const float* b2   = (const float*)d_in[10];
    const float* bng  = (const float*)d_in[11];
    const float* bnb  = (const float*)d_in[12];
    float* out = (float*)d_out;

    static int attr_done = 0;
    if (!attr_done) {
        cudaFuncSetAttribute(kA, cudaFuncAttributeMaxDynamicSharedMemorySize, KA_SMEM);
        cudaFuncSetAttribute(kB, cudaFuncAttributeMaxDynamicSharedMemorySize, KB_SMEM);
        attr_done = 1;
    }

    k_detect<<<1, 32>>>(x);
    k_embed<<<(N_NODES * 32 + 255) / 256, 256>>>(x, elem, chir);
    k_etab<<<9, 128>>>(bt, bd);
    k_zero_deg<<<(N_NODES + 255) / 256, 256>>>();
    k_hist<<<(N_EDGES + 255) / 256, 256>>>(ei);
    k_scan<<<1, 1024>>>();
    k_fill<<<(N_EDGES + 255) / 256, 256>>>(ei, ea);
    k_prep<<<128, 256>>>(W1, W2);

    for (int l = 0; l < NLAYERS; l++) {
        k_agg<<<(N_NODES + 7) / 8, 256>>>(l);
        kA<<<148, 256, KA_SMEM>>>(b1);
        kB<<<148, 256, KB_SMEM>>>(b2);
        k_stats<<<NT, 256>>>(bng + l * D, bnb + l * D);
    }
    k_final<<<(N_NODES * 32 + 255) / 256, 256>>>(out);
}

// round 7
// speedup vs baseline: 1.3239x; 1.0531x over previous
#include <cuda_runtime.h>

#define N_NODES 50000
#define N_EDGES 600000
#define D 128
#define NLAYERS 5
#define NT 391                    // ceil(50000/128) row tiles of 128

typedef unsigned long long ull;
typedef unsigned int u32;

// ----------------- persistent device scratch -----------------
__device__ float g_h[N_NODES * D];
__device__ float g_z[NT * 128 * D];
__device__ float g_out[N_NODES * D];
__device__ float g_etab[9 * D];
__device__ float g_stats[2 * D];
__device__ float g_aff[2 * D];
__device__ int   g_deg[N_NODES];
__device__ int   g_off[N_NODES + 1];
__device__ int   g_cur[N_NODES];
__device__ int   g_csr[N_EDGES];
__device__ int   g_is64;
// hidden activations per tile: hi plane [128][256] bf16 (65536B) + lo plane
__device__ __align__(16) unsigned char g_hid[(size_t)NT * 131072];
// weight images: [n][k] bf16, hi plane then lo plane (65536B each)
__device__ __align__(16) unsigned char g_w1T[131072];   // n=256, k=128
__device__ __align__(16) unsigned char g_w2T[131072];   // n=128, k=256

// ----------------- helpers -----------------
__device__ __forceinline__ u32 smem_u32(const void* p) {
    u32 a;
    asm("{ .reg .u64 t; cvta.to.shared.u64 t, %1; cvt.u32.u64 %0, t; }" : "=r"(a) : "l"(p));
    return a;
}
// split two floats into hi-pair / lo-pair bf16x2 words (x0 -> low half)
__device__ __forceinline__ void split2(float x0, float x1, u32& hp, u32& lp) {
    asm("cvt.rn.bf16x2.f32 %0, %1, %2;" : "=r"(hp) : "f"(x1), "f"(x0));
    float h0 = __uint_as_float(hp << 16);
    float h1 = __uint_as_float(hp & 0xffff0000u);
    float r0 = x0 - h0, r1 = x1 - h1;
    asm("cvt.rn.bf16x2.f32 %0, %1, %2;" : "=r"(lp) : "f"(r1), "f"(r0));
}
__device__ __forceinline__ void ldsm4(u32 addr, u32& r0, u32& r1, u32& r2, u32& r3) {
    asm volatile("ldmatrix.sync.aligned.m8n8.x4.shared.b16 {%0,%1,%2,%3}, [%4];"
                 : "=r"(r0), "=r"(r1), "=r"(r2), "=r"(r3) : "r"(addr));
}
__device__ __forceinline__ void mma16816(float* c, u32 a0, u32 a1, u32 a2, u32 a3,
                                         u32 b0, u32 b1) {
    asm volatile(
        "mma.sync.aligned.m16n8k16.row.col.f32.bf16.bf16.f32 "
        "{%0,%1,%2,%3}, {%4,%5,%6,%7}, {%8,%9}, {%0,%1,%2,%3};"
        : "+f"(c[0]), "+f"(c[1]), "+f"(c[2]), "+f"(c[3])
        : "r"(a0), "r"(a1), "r"(a2), "r"(a3), "r"(b0), "r"(b1));
}

__device__ __forceinline__ int getidx(const int* __restrict__ p, int i) {
    return g_is64 ? p[2 * i] : p[i];
}

// ----------------- setup -----------------
__global__ void k_detect(const int* __restrict__ x) {
    if (threadIdx.x == 0) {
        int nz = 0;
        for (int i = 1; i < 128; i += 2) nz |= x[i];
        g_is64 = (nz == 0) ? 1 : 0;
    }
}

__global__ void k_embed(const int* __restrict__ x,
                        const float* __restrict__ elem,
                        const float* __restrict__ chir) {
    int i = blockIdx.x * blockDim.x + threadIdx.x;
    if (i >= N_NODES * 32) return;
    int node = i >> 5, l = i & 31;
    int a = getidx(x, 2 * node);
    int c = getidx(x, 2 * node + 1);
    float4 va = __ldg((const float4*)(elem + a * D) + l);
    float4 vc = __ldg((const float4*)(chir + c * D) + l);
    ((float4*)(g_h + node * D))[l] =
        make_float4(va.x + vc.x, va.y + vc.y, va.z + vc.z, va.w + vc.w);
}

__global__ void k_etab(const float* __restrict__ bt, const float* __restrict__ bd) {
    int code = blockIdx.x, t = code / 3, d = code % 3, c = threadIdx.x;
    g_etab[code * D + c] = bt[t * D + c] + bd[d * D + c];
}

__global__ void k_zero_deg() {
    int i = blockIdx.x * blockDim.x + threadIdx.x;
    if (i < N_NODES) g_deg[i] = 0;
    if (blockIdx.x == 0 && threadIdx.x < 256) g_stats[threadIdx.x] = 0.f;
}

__global__ void k_hist(const int* __restrict__ ei) {
    int e = blockIdx.x * blockDim.x + threadIdx.x;
    if (e < N_EDGES) atomicAdd(&g_deg[getidx(ei, N_EDGES + e)], 1);
}

__global__ void k_scan() {
    __shared__ int sh[1024];
    __shared__ int carry_s;
    int tid = threadIdx.x;
    if (tid == 0) carry_s = 0;
    __syncthreads();
    for (int base = 0; base < N_NODES; base += 1024) {
        int i = base + tid;
        int v = (i < N_NODES) ? g_deg[i] : 0;
        sh[tid] = v;
        __syncthreads();
        for (int off = 1; off < 1024; off <<= 1) {
            int t = (tid >= off) ? sh[tid - off] : 0;
            __syncthreads();
            sh[tid] += t;
            __syncthreads();
        }
        int incl = sh[tid];
        int c = carry_s;
        if (i < N_NODES) { g_off[i] = c + incl - v; g_cur[i] = c + incl - v; }
        __syncthreads();
        if (tid == 1023) carry_s = c + incl;
        __syncthreads();
    }
    if (tid == 0) g_off[N_NODES] = carry_s;
}

__global__ void k_fill(const int* __restrict__ ei, const int* __restrict__ ea) {
    int e = blockIdx.x * blockDim.x + threadIdx.x;
    if (e < N_EDGES) {
        int src = getidx(ei, e);
        int dst = getidx(ei, N_EDGES + e);
        int t = getidx(ea, 2 * e);
        int d = getidx(ea, 2 * e + 1);
        int pos = atomicAdd(&g_cur[dst], 1);
        g_csr[pos] = src | ((t * 3 + d) << 20);
    }
}

// weight images: B[n][k] = W[k][n], split bf16 hi/lo planes
__global__ void k_prep(const float* __restrict__ W1, const float* __restrict__ W2) {
    int idx = blockIdx.x * blockDim.x + threadIdx.x;
    if (idx < 16384) {                        // W1: n 0..255, k pairs 0..63
        int n = idx >> 6, kp = idx & 63, k = kp * 2;
        float a = __ldg(W1 + k * 256 + n);
        float b = __ldg(W1 + (k + 1) * 256 + n);
        u32 hp, lp; split2(a, b, hp, lp);
        ((u32*)g_w1T)[n * 64 + kp] = hp;
        ((u32*)g_w1T)[16384 + n * 64 + kp] = lp;
    } else if (idx < 32768) {                 // W2: n 0..127, k pairs 0..127
        int q = idx - 16384;
        int n = q >> 7, kp = q & 127, k = kp * 2;
        float a = __ldg(W2 + k * 128 + n);
        float b = __ldg(W2 + (k + 1) * 128 + n);
        u32 hp, lp; split2(a, b, hp, lp);
        ((u32*)g_w2T)[n * 128 + kp] = hp;
        ((u32*)g_w2T)[16384 + n * 128 + kp] = lp;
    }
}

// ----------------- aggregation: one warp per dst node -----------------
__device__ __forceinline__ void agg_one(float4& acc, float4 hv, const float* et,
                                        int code, int c0, int mode,
                                        float4 sc, float4 sf) {
    if (mode) {
        hv.x = fmaxf(fmaf(hv.x, sc.x, sf.x), 0.f);
        hv.y = fmaxf(fmaf(hv.y, sc.y, sf.y), 0.f);
        hv.z = fmaxf(fmaf(hv.z, sc.z, sf.z), 0.f);
        hv.w = fmaxf(fmaf(hv.w, sc.w, sf.w), 0.f);
    }
    float4 ev = *(const float4*)(et + code * D + c0);
    acc.x += fmaxf(hv.x + ev.x, 0.f);
    acc.y += fmaxf(hv.y + ev.y, 0.f);
    acc.z += fmaxf(hv.z + ev.z, 0.f);
    acc.w += fmaxf(hv.w + ev.w, 0.f);
}

__global__ void __launch_bounds__(256) k_agg(int layer) {
    __shared__ float et[9 * D];
    __shared__ float aff[2 * D];
    int tid = threadIdx.x;
    for (int i = tid; i < 9 * D; i += 256) et[i] = g_etab[i];
    if (tid < 2 * D) aff[tid] = g_aff[tid];
    __syncthreads();

    const int mode = (layer > 0);
    const float* __restrict__ in = mode ? g_out : g_h;

    int warp = tid >> 5, lane = tid & 31;
    int node = blockIdx.x * 8 + warp;
    if (node >= N_NODES) return;
    int c0 = lane * 4;

    float4 sc = make_float4(1.f, 1.f, 1.f, 1.f);
    float4 sf = make_float4(0.f, 0.f, 0.f, 0.f);
    if (mode) { sc = *(float4*)&aff[c0]; sf = *(float4*)&aff[D + c0]; }

    int beg = g_off[node], end = g_off[node + 1];
    float4 acc = make_float4(0.f, 0.f, 0.f, 0.f);

    int e = beg;
    for (; e + 4 <= end; e += 4) {      // 4 gathers in flight per warp
        int v0 = __ldg(g_csr + e);
        int v1 = __ldg(g_csr + e + 1);
        int v2 = __ldg(g_csr + e + 2);
        int v3 = __ldg(g_csr + e + 3);
        float4 h0 = __ldg((const float4*)(in + (size_t)(v0 & 0xFFFFF) * D) + lane);
        float4 h1 = __ldg((const float4*)(in + (size_t)(v1 & 0xFFFFF) * D) + lane);
        float4 h2 = __ldg((const float4*)(in + (size_t)(v2 & 0xFFFFF) * D) + lane);
        float4 h3 = __ldg((const float4*)(in + (size_t)(v3 & 0xFFFFF) * D) + lane);
        agg_one(acc, h0, et, v0 >> 20, c0, mode, sc, sf);
        agg_one(acc, h1, et, v1 >> 20, c0, mode, sc, sf);
        agg_one(acc, h2, et, v2 >> 20, c0, mode, sc, sf);
        agg_one(acc, h3, et, v3 >> 20, c0, mode, sc, sf);
    }
    for (; e < end; e++) {
        int v = __ldg(g_csr + e);
        float4 hv = __ldg((const float4*)(in + (size_t)(v & 0xFFFFF) * D) + lane);
        agg_one(acc, hv, et, v >> 20, c0, mode, sc, sf);
    }

    float4 hd = __ldg((const float4*)(in + (size_t)node * D) + lane);
    if (mode) {
        hd.x = fmaxf(fmaf(hd.x, sc.x, sf.x), 0.f);
        hd.y = fmaxf(fmaf(hd.y, sc.y, sf.y), 0.f);
        hd.z = fmaxf(fmaf(hd.z, sc.z, sf.z), 0.f);
        hd.w = fmaxf(fmaf(hd.w, sc.w, sf.w), 0.f);
    }
    acc.x += hd.x; acc.y += hd.y; acc.z += hd.z; acc.w += hd.w;
    *(float4*)(g_z + (size_t)node * D + c0) = acc;
}

// ----------------- GEMM1: hidden = relu(z@W1+b1) -> split-bf16 planes -------
// smem: B hi/lo [256][272B], A hi/lo [128][272B], bias[256]
#define KA_B_HI 0
#define KA_B_LO 69632
#define KA_A_HI 139264
#define KA_A_LO 174080
#define KA_BIAS 208896
#define KA_SMEM 209920

__global__ void __launch_bounds__(256, 1) kA(const float* __restrict__ b1) {
    extern __shared__ char sm[];
    u32 sb = smem_u32(sm);
    const int tid = threadIdx.x;
    const int warp = tid >> 5, lane = tid & 31;

    // stage weights (once) + bias
    {
        const uint4* src = (const uint4*)g_w1T;
        for (int i = tid; i < 8192; i += 256) {
            int p = i >> 12, r = (i >> 4) & 255, w = i & 15;
            *(uint4*)(sm + KA_B_HI + p * 69632 + r * 272 + w * 16) =
                src[p * 4096 + r * 16 + w];
        }
        ((float*)(sm + KA_BIAS))[tid] = __ldg(b1 + tid);
    }
    __syncthreads();

    const int wr = warp >> 2, wc = warp & 3;        // 2 x 4 warp grid, 64x64 tiles
    const u32 aHi = sb + KA_A_HI + (wr * 64 + (lane & 15)) * 272 + (lane >> 4) * 16;
    const u32 aLo = aHi + (KA_A_LO - KA_A_HI);
    const u32 bHi = sb + KA_B_HI + (wc * 64 + (lane & 15)) * 272 + (lane >> 4) * 16;
    const u32 bLo = bHi + 69632;
    const float* bias = (const float*)(sm + KA_BIAS);

    for (int tile = blockIdx.x; tile < NT; tile += gridDim.x) {
        // stage A: z fp32 -> split bf16 hi/lo
        for (int i = tid; i < 4096; i += 256) {
            int r = i >> 5, c4 = i & 31;
            int row = tile * 128 + r;
            float4 v = make_float4(0.f, 0.f, 0.f, 0.f);
            if (row < N_NODES) v = __ldg((const float4*)(g_z + (size_t)row * D) + c4);
            u32 h0, l0, h1, l1;
            split2(v.x, v.y, h0, l0);
            split2(v.z, v.w, h1, l1);
            *(ull*)(sm + KA_A_HI + r * 272 + c4 * 8) = (ull)h0 | ((ull)h1 << 32);
            *(ull*)(sm + KA_A_LO + r * 272 + c4 * 8) = (ull)l0 | ((ull)l1 << 32);
        }
        __syncthreads();

        float acc[4][8][4];
#pragma unroll
        for (int a = 0; a < 4; a++)
#pragma unroll
            for (int b = 0; b < 8; b++)
#pragma unroll
                for (int c = 0; c < 4; c++) acc[a][b][c] = 0.f;

        for (int ks = 0; ks < 8; ks++) {
            const u32 ko = ks * 32;
            u32 ah[4][4], al[4][4];
#pragma unroll
            for (int mt = 0; mt < 4; mt++) {
                ldsm4(aHi + mt * (16 * 272) + ko, ah[mt][0], ah[mt][1], ah[mt][2], ah[mt][3]);
                ldsm4(aLo + mt * (16 * 272) + ko, al[mt][0], al[mt][1], al[mt][2], al[mt][3]);
            }
#pragma unroll
            for (int g = 0; g < 4; g++) {
                u32 bh0, bh1, bh2, bh3, bl0, bl1, bl2, bl3;
                ldsm4(bHi + g * (16 * 272) + ko, bh0, bh1, bh2, bh3);
                ldsm4(bLo + g * (16 * 272) + ko, bl0, bl1, bl2, bl3);
#pragma unroll
                for (int mt = 0; mt < 4; mt++) {
                    mma16816(acc[mt][2 * g],     ah[mt][0], ah[mt][1], ah[mt][2], ah[mt][3], bh0, bh2);
                    mma16816(acc[mt][2 * g + 1], ah[mt][0], ah[mt][1], ah[mt][2], ah[mt][3], bh1, bh3);
                    mma16816(acc[mt][2 * g],     ah[mt][0], ah[mt][1], ah[mt][2], ah[mt][3], bl0, bl2);
                    mma16816(acc[mt][2 * g + 1], ah[mt][0], ah[mt][1], ah[mt][2], ah[mt][3], bl1, bl3);
                    mma16816(acc[mt][2 * g],     al[mt][0], al[mt][1], al[mt][2], al[mt][3], bh0, bh2);
                    mma16816(acc[mt][2 * g + 1], al[mt][0], al[mt][1], al[mt][2], al[mt][3], bh1, bh3);
                }
            }
        }

        // epilogue: bias + relu + re-split -> g_hid planes
        u32* hidHi = (u32*)(g_hid + (size_t)tile * 131072);
        u32* hidLo = hidHi + 16384;
        const int m0 = wr * 64, n0 = wc * 64;
#pragma unroll
        for (int mt = 0; mt < 4; mt++)
#pragma unroll
            for (int nt = 0; nt < 8; nt++) {
                int col = n0 + nt * 8 + 2 * (lane & 3);
                int r0 = m0 + mt * 16 + (lane >> 2);
                float bv0 = bias[col], bv1 = bias[col + 1];
                u32 hp, lp;
                float v0 = fmaxf(acc[mt][nt][0] + bv0, 0.f);
                float v1 = fmaxf(acc[mt][nt][1] + bv1, 0.f);
                split2(v0, v1, hp, lp);
                hidHi[r0 * 128 + (col >> 1)] = hp;
                hidLo[r0 * 128 + (col >> 1)] = lp;
                v0 = fmaxf(acc[mt][nt][2] + bv0, 0.f);
                v1 = fmaxf(acc[mt][nt][3] + bv1, 0.f);
                split2(v0, v1, hp, lp);
                hidHi[(r0 + 8) * 128 + (col >> 1)] = hp;
                hidLo[(r0 + 8) * 128 + (col >> 1)] = lp;
            }
        __syncthreads();
    }
}

// ----------------- GEMM2: g_out = hidden @ W2 + b2, fused BN stats ----------
// smem: B hi/lo [128][528B], A hi/lo [128][272B] (half-K staged), bias[128]
#define KB_B_HI 0
#define KB_B_LO 67584
#define KB_A_HI 135168
#define KB_A_LO 169984
#define KB_BIAS 204800
#define KB_SMEM 205312

__global__ void __launch_bounds__(256, 1) kB(const float* __restrict__ b2) {
    extern __shared__ char sm[];
    u32 sb = smem_u32(sm);
    const int tid = threadIdx.x;
    const int warp = tid >> 5, lane = tid & 31;

    {
        const uint4* src = (const uint4*)g_w2T;
        for (int i = tid; i < 8192; i += 256) {
            int p = i >> 12, r = (i >> 5) & 127, w = i & 31;
            *(uint4*)(sm + KB_B_HI + p * 67584 + r * 528 + w * 16) =
                src[p * 4096 + r * 32 + w];
        }
        if (tid < 128) ((float*)(sm + KB_BIAS))[tid] = __ldg(b2 + tid);
    }
    __syncthreads();

    const int wr = warp >> 2, wc = warp & 3;        // 2 x 4 grid, 64x32 tiles
    const u32 aHi = sb + KB_A_HI + (wr * 64 + (lane & 15)) * 272 + (lane >> 4) * 16;
    const u32 aLo = aHi + (KB_A_LO - KB_A_HI);
    const u32 bHi = sb + KB_B_HI + (wc * 32 + (lane & 15)) * 528 + (lane >> 4) * 16;
    const u32 bLo = bHi + 67584;
    const float* bias = (const float*)(sm + KB_BIAS);

    // BN stat accumulators: this thread's columns are fixed across tiles
    float st_s[4][2], st_s2[4][2];
#pragma unroll
    for (int nt = 0; nt < 4; nt++) {
        st_s[nt][0] = st_s[nt][1] = 0.f;
        st_s2[nt][0] = st_s2[nt][1] = 0.f;
    }

    for (int tile = blockIdx.x; tile < NT; tile += gridDim.x) {
        float acc[4][4][4];
#pragma unroll
        for (int a = 0; a < 4; a++)
#pragma unroll
            for (int b = 0; b < 4; b++)
#pragma unroll
                for (int c = 0; c < 4; c++) acc[a][b][c] = 0.f;

        for (int pass = 0; pass < 2; pass++) {
            // stage A half-K: linear copy from g_hid planes into padded smem
            for (int i = tid; i < 4096; i += 256) {
                int p = i >> 11, r = (i >> 4) & 127, w = i & 15;
                *(uint4*)(sm + KB_A_HI + p * 34816 + r * 272 + w * 16) =
                    ((const uint4*)(g_hid + (size_t)tile * 131072 + p * 65536))
                        [r * 32 + pass * 16 + w];
            }
            __syncthreads();

            for (int ks = 0; ks < 8; ks++) {
                const u32 ko = ks * 32;
                const u32 bo = pass * 256 + ko;
                u32 ah[4][4], al[4][4];
#pragma unroll
                for (int mt = 0; mt < 4; mt++) {
                    ldsm4(aHi + mt * (16 * 272) + ko, ah[mt][0], ah[mt][1], ah[mt][2], ah[mt][3]);
                    ldsm4(aLo + mt * (16 * 272) + ko, al[mt][0], al[mt][1], al[mt][2], al[mt][3]);
                }
#pragma unroll
                for (int g = 0; g < 2; g++) {
                    u32 bh0, bh1, bh2, bh3, bl0, bl1, bl2, bl3;
                    ldsm4(bHi + g * (16 * 528) + bo, bh0, bh1, bh2, bh3);
                    ldsm4(bLo + g * (16 * 528) + bo, bl0, bl1, bl2, bl3);
#pragma unroll
                    for (int mt = 0; mt < 4; mt++) {
                        mma16816(acc[mt][2 * g],     ah[mt][0], ah[mt][1], ah[mt][2], ah[mt][3], bh0, bh2);
                        mma16816(acc[mt][2 * g + 1], ah[mt][0], ah[mt][1], ah[mt][2], ah[mt][3], bh1, bh3);
                        mma16816(acc[mt][2 * g],     ah[mt][0], ah[mt][1], ah[mt][2], ah[mt][3], bl0, bl2);
                        mma16816(acc[mt][2 * g + 1], ah[mt][0], ah[mt][1], ah[mt][2], ah[mt][3], bl1, bl3);
                        mma16816(acc[mt][2 * g],     al[mt][0], al[mt][1], al[mt][2], al[mt][3], bh0, bh2);
                        mma16816(acc[mt][2 * g + 1], al[mt][0], al[mt][1], al[mt][2], al[mt][3], bh1, bh3);
                    }
                }
            }
            __syncthreads();
        }

        // epilogue: bias, write fp32 g_out, accumulate BN stats in registers
        const int m0 = wr * 64, n0 = wc * 32;
#pragma unroll
        for (int mt = 0; mt < 4; mt++)
#pragma unroll
            for (int nt = 0; nt < 4; nt++) {
                int col = n0 + nt * 8 + 2 * (lane & 3);
                int r0 = tile * 128 + m0 + mt * 16 + (lane >> 2);
                float bv0 = bias[col], bv1 = bias[col + 1];
                if (r0 < N_NODES) {
                    float o0 = acc[mt][nt][0] + bv0;
                    float o1 = acc[mt][nt][1] + bv1;
                    *(float2*)(g_out + (size_t)r0 * D + col) = make_float2(o0, o1);
                    st_s[nt][0] += o0;  st_s2[nt][0] += o0 * o0;
                    st_s[nt][1] += o1;  st_s2[nt][1] += o1 * o1;
                }
                if (r0 + 8 < N_NODES) {
                    float o0 = acc[mt][nt][2] + bv0;
                    float o1 = acc[mt][nt][3] + bv1;
                    *(float2*)(g_out + (size_t)(r0 + 8) * D + col) = make_float2(o0, o1);
                    st_s[nt][0] += o0;  st_s2[nt][0] += o0 * o0;
                    st_s[nt][1] += o1;  st_s2[nt][1] += o1 * o1;
                }
            }
    }

    // reduce stats across the 8 lane-groups sharing columns (lane stride 4)
#pragma unroll
    for (int nt = 0; nt < 4; nt++)
#pragma unroll
        for (int p = 0; p < 2; p++) {
#pragma unroll
            for (int off = 16; off >= 4; off >>= 1) {
                st_s[nt][p]  += __shfl_xor_sync(0xffffffffu, st_s[nt][p],  off);
                st_s2[nt][p] += __shfl_xor_sync(0xffffffffu, st_s2[nt][p], off);
            }
        }
    if (lane < 4) {
        const int n0 = wc * 32;
#pragma unroll
        for (int nt = 0; nt < 4; nt++) {
            int col = n0 + nt * 8 + 2 * lane;
            atomicAdd(&g_stats[col],           st_s[nt][0]);
            atomicAdd(&g_stats[col + 1],       st_s[nt][1]);
            atomicAdd(&g_stats[128 + col],     st_s2[nt][0]);
            atomicAdd(&g_stats[128 + col + 1], st_s2[nt][1]);
        }
    }
}

// ----------------- BN fold: stats -> per-feature scale/shift, self-reset ----
__global__ void k_bnfold(const float* __restrict__ gamma, const float* __restrict__ beta) {
    int c = threadIdx.x;
    if (c < D) {
        float sum = g_stats[c], sum2 = g_stats[128 + c];
        const float invN = 1.0f / (float)N_NODES;
        float mean = sum * invN;
        float var = sum2 * invN - mean * mean;
        float scl = rsqrtf(var + 1e-5f) * __ldg(gamma + c);
        g_aff[c] = scl;
        g_aff[128 + c] = __ldg(beta + c) - mean * scl;
        g_stats[c] = 0.f;
        g_stats[128 + c] = 0.f;
    }
}

// ----------------- final: apply last BN (no relu) -> d_out ------------------
__global__ void k_final(float* __restrict__ out) {
    int i = blockIdx.x * blockDim.x + threadIdx.x;
    if (i >= N_NODES * 32) return;
    int c0 = (i & 31) * 4;
    float4 v = ((const float4*)g_out)[i];
    float4 sc = *(const float4*)&g_aff[c0];
    float4 sf = *(const float4*)&g_aff[D + c0];
    v.x = fmaf(v.x, sc.x, sf.x);
    v.y = fmaf(v.y, sc.y, sf.y);
    v.z = fmaf(v.z, sc.z, sf.z);
    v.w = fmaf(v.w, sc.w, sf.w);
    ((float4*)out)[i] = v;
}

// ----------------- launch -----------------
extern "C" void kernel_launch(void* const* d_in, const int* in_sizes, int n_in,
                              void* d_out, int out_size) {
    const int*   x    = (const int*)d_in[0];
    const int*   ei   = (const int*)d_in[1];
    const int*   ea   = (const int*)d_in[2];
    const float* elem = (const float*)d_in[3];
    const float* chir = (const float*)d_in[4];
    const float* bt   = (const float*)d_in[5];
    const float* bd   = (const float*)d_in[6];
    const float* W1   = (const float*)d_in[7];
    const float* b1   = (const float*)d_in[8];
    const float* W2   = (const float*)d_in[9];
    const float* b2   = (const float*)d_in[10];
    const float* bng  = (const float*)d_in[11];
    const float* bnb  = (const float*)d_in[12];
    float* out = (float*)d_out;

    static int attr_done = 0;
    if (!attr_done) {
        cudaFuncSetAttribute(kA, cudaFuncAttributeMaxDynamicSharedMemorySize, KA_SMEM);
        cudaFuncSetAttribute(kB, cudaFuncAttributeMaxDynamicSharedMemorySize, KB_SMEM);
        attr_done = 1;
    }

    k_detect<<<1, 32>>>(x);
    k_embed<<<(N_NODES * 32 + 255) / 256, 256>>>(x, elem, chir);
    k_etab<<<9, 128>>>(bt, bd);
    k_zero_deg<<<(N_NODES + 255) / 256, 256>>>();
    k_hist<<<(N_EDGES + 255) / 256, 256>>>(ei);
    k_scan<<<1, 1024>>>();
    k_fill<<<(N_EDGES + 255) / 256, 256>>>(ei, ea);
    k_prep<<<128, 256>>>(W1, W2);

    for (int l = 0; l < NLAYERS; l++) {
        k_agg<<<(N_NODES + 7) / 8, 256>>>(l);
        kA<<<148, 256, KA_SMEM>>>(b1);
        kB<<<148, 256, KB_SMEM>>>(b2);
        k_bnfold<<<1, 128>>>(bng + l * D, bnb + l * D);
    }
    k_final<<<(N_NODES * 32 + 255) / 256, 256>>>(out);
}

// round 8
// speedup vs baseline: 1.4336x; 1.0828x over previous
#include <cuda_runtime.h>

#define N_NODES 50000
#define N_EDGES 600000
#define D 128
#define NLAYERS 5
#define NT 391                    // ceil(50000/128) row tiles of 128

typedef unsigned long long ull;
typedef unsigned int u32;

// ----------------- persistent device scratch -----------------
__device__ float g_h[N_NODES * D];
__device__ float g_z[NT * 128 * D];
__device__ float g_out[N_NODES * D];
__device__ float g_etab[9 * D];
__device__ float g_stats[2 * D];
__device__ float g_aff[2 * D];
__device__ int   g_deg[N_NODES];
__device__ int   g_off[N_NODES + 1];
__device__ int   g_cur[N_NODES];
__device__ int   g_csr[N_EDGES];
__device__ int   g_is64;
// hidden activations per tile: [row(128)][colpair(128)] ull = (hi_u32 | lo_u32<<32)
__device__ __align__(16) unsigned char g_hid[(size_t)NT * 131072];
// weight images: [n][k] bf16, hi plane then lo plane (65536B each)
__device__ __align__(16) unsigned char g_w1T[131072];   // n=256, k=128
__device__ __align__(16) unsigned char g_w2T[131072];   // n=128, k=256

// ----------------- helpers -----------------
__device__ __forceinline__ u32 smem_u32(const void* p) {
    u32 a;
    asm("{ .reg .u64 t; cvta.to.shared.u64 t, %1; cvt.u32.u64 %0, t; }" : "=r"(a) : "l"(p));
    return a;
}
// split two floats into hi-pair / lo-pair bf16x2 words (x0 -> low half)
__device__ __forceinline__ void split2(float x0, float x1, u32& hp, u32& lp) {
    asm("cvt.rn.bf16x2.f32 %0, %1, %2;" : "=r"(hp) : "f"(x1), "f"(x0));
    float h0 = __uint_as_float(hp << 16);
    float h1 = __uint_as_float(hp & 0xffff0000u);
    float r0 = x0 - h0, r1 = x1 - h1;
    asm("cvt.rn.bf16x2.f32 %0, %1, %2;" : "=r"(lp) : "f"(r1), "f"(r0));
}
__device__ __forceinline__ void ldsm4(u32 addr, u32& r0, u32& r1, u32& r2, u32& r3) {
    asm volatile("ldmatrix.sync.aligned.m8n8.x4.shared.b16 {%0,%1,%2,%3}, [%4];"
                 : "=r"(r0), "=r"(r1), "=r"(r2), "=r"(r3) : "r"(addr));
}
__device__ __forceinline__ void mma16816(float* c, u32 a0, u32 a1, u32 a2, u32 a3,
                                         u32 b0, u32 b1) {
    asm volatile(
        "mma.sync.aligned.m16n8k16.row.col.f32.bf16.bf16.f32 "
        "{%0,%1,%2,%3}, {%4,%5,%6,%7}, {%8,%9}, {%0,%1,%2,%3};"
        : "+f"(c[0]), "+f"(c[1]), "+f"(c[2]), "+f"(c[3])
        : "r"(a0), "r"(a1), "r"(a2), "r"(a3), "r"(b0), "r"(b1));
}

__device__ __forceinline__ int getidx(const int* __restrict__ p, int i) {
    return g_is64 ? p[2 * i] : p[i];
}

// ----------------- merged setup: detect + etab + zero(deg,stats) ------------
__global__ void k_init(const int* __restrict__ x,
                       const float* __restrict__ bt,
                       const float* __restrict__ bd) {
    int i = blockIdx.x * blockDim.x + threadIdx.x;
    if (i < N_NODES) g_deg[i] = 0;
    if (blockIdx.x == 0 && threadIdx.x < 256) g_stats[threadIdx.x] = 0.f;
    if (blockIdx.x == 1 && threadIdx.x == 0) {
        int nz = 0;
        for (int j = 1; j < 128; j += 2) nz |= x[j];
        g_is64 = (nz == 0) ? 1 : 0;
    }
    if (blockIdx.x >= 2 && blockIdx.x < 11 && threadIdx.x < 128) {
        int code = blockIdx.x - 2, t = code / 3, d = code % 3, c = threadIdx.x;
        g_etab[code * D + c] = bt[t * D + c] + bd[d * D + c];
    }
}

__global__ void k_embed(const int* __restrict__ x,
                        const float* __restrict__ elem,
                        const float* __restrict__ chir) {
    int i = blockIdx.x * blockDim.x + threadIdx.x;
    if (i >= N_NODES * 32) return;
    int node = i >> 5, l = i & 31;
    int a = getidx(x, 2 * node);
    int c = getidx(x, 2 * node + 1);
    float4 va = __ldg((const float4*)(elem + a * D) + l);
    float4 vc = __ldg((const float4*)(chir + c * D) + l);
    ((float4*)(g_h + node * D))[l] =
        make_float4(va.x + vc.x, va.y + vc.y, va.z + vc.z, va.w + vc.w);
}

__global__ void k_hist(const int* __restrict__ ei) {
    int e = blockIdx.x * blockDim.x + threadIdx.x;
    if (e < N_EDGES) atomicAdd(&g_deg[getidx(ei, N_EDGES + e)], 1);
}

__global__ void k_scan() {
    __shared__ int sh[1024];
    __shared__ int carry_s;
    int tid = threadIdx.x;
    if (tid == 0) carry_s = 0;
    __syncthreads();
    for (int base = 0; base < N_NODES; base += 1024) {
        int i = base + tid;
        int v = (i < N_NODES) ? g_deg[i] : 0;
        sh[tid] = v;
        __syncthreads();
        for (int off = 1; off < 1024; off <<= 1) {
            int t = (tid >= off) ? sh[tid - off] : 0;
            __syncthreads();
            sh[tid] += t;
            __syncthreads();
        }
        int incl = sh[tid];
        int c = carry_s;
        if (i < N_NODES) { g_off[i] = c + incl - v; g_cur[i] = c + incl - v; }
        __syncthreads();
        if (tid == 1023) carry_s = c + incl;
        __syncthreads();
    }
    if (tid == 0) g_off[N_NODES] = carry_s;
}

__global__ void k_fill(const int* __restrict__ ei, const int* __restrict__ ea) {
    int e = blockIdx.x * blockDim.x + threadIdx.x;
    if (e < N_EDGES) {
        int src = getidx(ei, e);
        int dst = getidx(ei, N_EDGES + e);
        int t = getidx(ea, 2 * e);
        int d = getidx(ea, 2 * e + 1);
        int pos = atomicAdd(&g_cur[dst], 1);
        g_csr[pos] = src | ((t * 3 + d) << 20);
    }
}

// weight images: B[n][k] = W[k][n], split bf16 hi/lo planes
__global__ void k_prep(const float* __restrict__ W1, const float* __restrict__ W2) {
    int idx = blockIdx.x * blockDim.x + threadIdx.x;
    if (idx < 16384) {                        // W1: n 0..255, k pairs 0..63
        int n = idx >> 6, kp = idx & 63, k = kp * 2;
        float a = __ldg(W1 + k * 256 + n);
        float b = __ldg(W1 + (k + 1) * 256 + n);
        u32 hp, lp; split2(a, b, hp, lp);
        ((u32*)g_w1T)[n * 64 + kp] = hp;
        ((u32*)g_w1T)[16384 + n * 64 + kp] = lp;
    } else if (idx < 32768) {                 // W2: n 0..127, k pairs 0..127
        int q = idx - 16384;
        int n = q >> 7, kp = q & 127, k = kp * 2;
        float a = __ldg(W2 + k * 128 + n);
        float b = __ldg(W2 + (k + 1) * 128 + n);
        u32 hp, lp; split2(a, b, hp, lp);
        ((u32*)g_w2T)[n * 128 + kp] = hp;
        ((u32*)g_w2T)[16384 + n * 128 + kp] = lp;
    }
}

// ----------------- aggregation: one warp per dst node -----------------
__device__ __forceinline__ void agg_one(float4& acc, float4 hv, const float* et,
                                        int code, int c0, int mode,
                                        float4 sc, float4 sf) {
    if (mode) {
        hv.x = fmaxf(fmaf(hv.x, sc.x, sf.x), 0.f);
        hv.y = fmaxf(fmaf(hv.y, sc.y, sf.y), 0.f);
        hv.z = fmaxf(fmaf(hv.z, sc.z, sf.z), 0.f);
        hv.w = fmaxf(fmaf(hv.w, sc.w, sf.w), 0.f);
    }
    float4 ev = *(const float4*)(et + code * D + c0);
    acc.x += fmaxf(hv.x + ev.x, 0.f);
    acc.y += fmaxf(hv.y + ev.y, 0.f);
    acc.z += fmaxf(hv.z + ev.z, 0.f);
    acc.w += fmaxf(hv.w + ev.w, 0.f);
}

__global__ void __launch_bounds__(256) k_agg(int layer) {
    __shared__ float et[9 * D];
    __shared__ float aff[2 * D];
    int tid = threadIdx.x;
    for (int i = tid; i < 9 * D; i += 256) et[i] = g_etab[i];
    if (tid < 2 * D) aff[tid] = g_aff[tid];
    __syncthreads();

    const int mode = (layer > 0);
    const float* __restrict__ in = mode ? g_out : g_h;

    int warp = tid >> 5, lane = tid & 31;
    int node = blockIdx.x * 8 + warp;
    if (node >= N_NODES) return;
    int c0 = lane * 4;

    float4 sc = make_float4(1.f, 1.f, 1.f, 1.f);
    float4 sf = make_float4(0.f, 0.f, 0.f, 0.f);
    if (mode) { sc = *(float4*)&aff[c0]; sf = *(float4*)&aff[D + c0]; }

    int beg = g_off[node], end = g_off[node + 1];
    float4 acc = make_float4(0.f, 0.f, 0.f, 0.f);

    int e = beg;
    for (; e + 4 <= end; e += 4) {
        int v0 = __ldg(g_csr + e);
        int v1 = __ldg(g_csr + e + 1);
        int v2 = __ldg(g_csr + e + 2);
        int v3 = __ldg(g_csr + e + 3);
        float4 h0 = __ldg((const float4*)(in + (size_t)(v0 & 0xFFFFF) * D) + lane);
        float4 h1 = __ldg((const float4*)(in + (size_t)(v1 & 0xFFFFF) * D) + lane);
        float4 h2 = __ldg((const float4*)(in + (size_t)(v2 & 0xFFFFF) * D) + lane);
        float4 h3 = __ldg((const float4*)(in + (size_t)(v3 & 0xFFFFF) * D) + lane);
        agg_one(acc, h0, et, v0 >> 20, c0, mode, sc, sf);
        agg_one(acc, h1, et, v1 >> 20, c0, mode, sc, sf);
        agg_one(acc, h2, et, v2 >> 20, c0, mode, sc, sf);
        agg_one(acc, h3, et, v3 >> 20, c0, mode, sc, sf);
    }
    for (; e < end; e++) {
        int v = __ldg(g_csr + e);
        float4 hv = __ldg((const float4*)(in + (size_t)(v & 0xFFFFF) * D) + lane);
        agg_one(acc, hv, et, v >> 20, c0, mode, sc, sf);
    }

    float4 hd = __ldg((const float4*)(in + (size_t)node * D) + lane);
    if (mode) {
        hd.x = fmaxf(fmaf(hd.x, sc.x, sf.x), 0.f);
        hd.y = fmaxf(fmaf(hd.y, sc.y, sf.y), 0.f);
        hd.z = fmaxf(fmaf(hd.z, sc.z, sf.z), 0.f);
        hd.w = fmaxf(fmaf(hd.w, sc.w, sf.w), 0.f);
    }
    acc.x += hd.x; acc.y += hd.y; acc.z += hd.z; acc.w += hd.w;
    *(float4*)(g_z + (size_t)node * D + c0) = acc;
}

// ----------------- GEMM1: hidden = relu(z@W1+b1) -> interleaved hi/lo -------
// smem: B hi/lo [256][272B], A hi/lo [128][272B], bias[256]
#define KA_B_HI 0
#define KA_B_LO 69632
#define KA_A_HI 139264
#define KA_A_LO 174080
#define KA_BIAS 208896
#define KA_SMEM 209920

__global__ void __launch_bounds__(512, 1) kA(const float* __restrict__ b1) {
    extern __shared__ char sm[];
    u32 sb = smem_u32(sm);
    const int tid = threadIdx.x;
    const int warp = tid >> 5, lane = tid & 31;

    // stage weights (once) + bias
    {
        const uint4* src = (const uint4*)g_w1T;
        for (int i = tid; i < 8192; i += 512) {
            int p = i >> 12, r = (i >> 4) & 255, w = i & 15;
            *(uint4*)(sm + KA_B_HI + p * 69632 + r * 272 + w * 16) =
                src[p * 4096 + r * 16 + w];
        }
        if (tid < 256) ((float*)(sm + KA_BIAS))[tid] = __ldg(b1 + tid);
    }
    __syncthreads();

    const int wr = warp >> 2, wc = warp & 3;        // 4 x 4 warp grid, 32x64 tiles
    const u32 aHi = sb + KA_A_HI + (wr * 32 + (lane & 15)) * 272 + (lane >> 4) * 16;
    const u32 aLo = aHi + (KA_A_LO - KA_A_HI);
    const u32 bHi = sb + KA_B_HI + (wc * 64 + (lane & 15)) * 272 + (lane >> 4) * 16;
    const u32 bLo = bHi + 69632;
    const float* bias = (const float*)(sm + KA_BIAS);

    for (int tile = blockIdx.x; tile < NT; tile += gridDim.x) {
        // stage A: z fp32 -> split bf16 hi/lo
        for (int i = tid; i < 4096; i += 512) {
            int r = i >> 5, c4 = i & 31;
            int row = tile * 128 + r;
            float4 v = make_float4(0.f, 0.f, 0.f, 0.f);
            if (row < N_NODES) v = __ldg((const float4*)(g_z + (size_t)row * D) + c4);
            u32 h0, l0, h1, l1;
            split2(v.x, v.y, h0, l0);
            split2(v.z, v.w, h1, l1);
            *(ull*)(sm + KA_A_HI + r * 272 + c4 * 8) = (ull)h0 | ((ull)h1 << 32);
            *(ull*)(sm + KA_A_LO + r * 272 + c4 * 8) = (ull)l0 | ((ull)l1 << 32);
        }
        __syncthreads();

        float acc[2][8][4];
#pragma unroll
        for (int a = 0; a < 2; a++)
#pragma unroll
            for (int b = 0; b < 8; b++)
#pragma unroll
                for (int c = 0; c < 4; c++) acc[a][b][c] = 0.f;

        for (int ks = 0; ks < 8; ks++) {
            const u32 ko = ks * 32;
            u32 ah[2][4], al[2][4];
#pragma unroll
            for (int mt = 0; mt < 2; mt++) {
                ldsm4(aHi + mt * (16 * 272) + ko, ah[mt][0], ah[mt][1], ah[mt][2], ah[mt][3]);
                ldsm4(aLo + mt * (16 * 272) + ko, al[mt][0], al[mt][1], al[mt][2], al[mt][3]);
            }
#pragma unroll
            for (int g = 0; g < 4; g++) {
                u32 bh0, bh1, bh2, bh3, bl0, bl1, bl2, bl3;
                ldsm4(bHi + g * (16 * 272) + ko, bh0, bh1, bh2, bh3);
                ldsm4(bLo + g * (16 * 272) + ko, bl0, bl1, bl2, bl3);
#pragma unroll
                for (int mt = 0; mt < 2; mt++) {
                    mma16816(acc[mt][2 * g],     ah[mt][0], ah[mt][1], ah[mt][2], ah[mt][3], bh0, bh2);
                    mma16816(acc[mt][2 * g + 1], ah[mt][0], ah[mt][1], ah[mt][2], ah[mt][3], bh1, bh3);
                    mma16816(acc[mt][2 * g],     ah[mt][0], ah[mt][1], ah[mt][2], ah[mt][3], bl0, bl2);
                    mma16816(acc[mt][2 * g + 1], ah[mt][0], ah[mt][1], ah[mt][2], ah[mt][3], bl1, bl3);
                    mma16816(acc[mt][2 * g],     al[mt][0], al[mt][1], al[mt][2], al[mt][3], bh0, bh2);
                    mma16816(acc[mt][2 * g + 1], al[mt][0], al[mt][1], al[mt][2], al[mt][3], bh1, bh3);
                }
            }
        }

        // epilogue: bias + relu + re-split -> interleaved (hi,lo) ull stores
        ull* hid64 = (ull*)(g_hid + (size_t)tile * 131072);
        const int m0 = wr * 32, n0 = wc * 64;
#pragma unroll
        for (int mt = 0; mt < 2; mt++)
#pragma unroll
            for (int nt = 0; nt < 8; nt++) {
                int col = n0 + nt * 8 + 2 * (lane & 3);
                int r0 = m0 + mt * 16 + (lane >> 2);
                float bv0 = bias[col], bv1 = bias[col + 1];
                u32 hp, lp;
                float v0 = fmaxf(acc[mt][nt][0] + bv0, 0.f);
                float v1 = fmaxf(acc[mt][nt][1] + bv1, 0.f);
                split2(v0, v1, hp, lp);
                hid64[r0 * 128 + (col >> 1)] = (ull)hp | ((ull)lp << 32);
                v0 = fmaxf(acc[mt][nt][2] + bv0, 0.f);
                v1 = fmaxf(acc[mt][nt][3] + bv1, 0.f);
                split2(v0, v1, hp, lp);
                hid64[(r0 + 8) * 128 + (col >> 1)] = (ull)hp | ((ull)lp << 32);
            }
        __syncthreads();
    }
}

// ----------------- GEMM2: g_out = hidden @ W2 + b2, fused BN stats ----------
// smem: B hi/lo [128][528B], A hi/lo [128][272B] (half-K staged), bias[128]
#define KB_B_HI 0
#define KB_B_LO 67584
#define KB_A_HI 135168
#define KB_A_LO 169984
#define KB_BIAS 204800
#define KB_SMEM 205312

__global__ void __launch_bounds__(512, 1) kB(const float* __restrict__ b2) {
    extern __shared__ char sm[];
    u32 sb = smem_u32(sm);
    const int tid = threadIdx.x;
    const int warp = tid >> 5, lane = tid & 31;

    {
        const uint4* src = (const uint4*)g_w2T;
        for (int i = tid; i < 8192; i += 512) {
            int p = i >> 12, r = (i >> 5) & 127, w = i & 31;
            *(uint4*)(sm + KB_B_HI + p * 67584 + r * 528 + w * 16) =
                src[p * 4096 + r * 32 + w];
        }
        if (tid < 128) ((float*)(sm + KB_BIAS))[tid] = __ldg(b2 + tid);
    }
    __syncthreads();

    const int wr = warp >> 2, wc = warp & 3;        // 4 x 4 grid, 32x32 tiles
    const u32 aHi = sb + KB_A_HI + (wr * 32 + (lane & 15)) * 272 + (lane >> 4) * 16;
    const u32 aLo = aHi + (KB_A_LO - KB_A_HI);
    const u32 bHi = sb + KB_B_HI + (wc * 32 + (lane & 15)) * 528 + (lane >> 4) * 16;
    const u32 bLo = bHi + 67584;
    const float* bias = (const float*)(sm + KB_BIAS);

    // BN stat accumulators: this thread's columns are fixed across tiles
    float st_s[4][2], st_s2[4][2];
#pragma unroll
    for (int nt = 0; nt < 4; nt++) {
        st_s[nt][0] = st_s[nt][1] = 0.f;
        st_s2[nt][0] = st_s2[nt][1] = 0.f;
    }

    for (int tile = blockIdx.x; tile < NT; tile += gridDim.x) {
        float acc[2][4][4];
#pragma unroll
        for (int a = 0; a < 2; a++)
#pragma unroll
            for (int b = 0; b < 4; b++)
#pragma unroll
                for (int c = 0; c < 4; c++) acc[a][b][c] = 0.f;

        const ull* hid64 = (const ull*)(g_hid + (size_t)tile * 131072);
        for (int pass = 0; pass < 2; pass++) {
            // stage A half-K: de-interleave (hi,lo) ull -> hi/lo planes
            for (int i = tid; i < 8192; i += 512) {
                int r = i >> 6, cp = i & 63;
                ull v = __ldg(hid64 + r * 128 + pass * 64 + cp);
                *(u32*)(sm + KB_A_HI + r * 272 + cp * 4) = (u32)v;
                *(u32*)(sm + KB_A_LO + r * 272 + cp * 4) = (u32)(v >> 32);
            }
            __syncthreads();

            for (int ks = 0; ks < 8; ks++) {
                const u32 ko = ks * 32;
                const u32 bo = pass * 256 + ko;
                u32 ah[2][4], al[2][4];
#pragma unroll
                for (int mt = 0; mt < 2; mt++) {
                    ldsm4(aHi + mt * (16 * 272) + ko, ah[mt][0], ah[mt][1], ah[mt][2], ah[mt][3]);
                    ldsm4(aLo + mt * (16 * 272) + ko, al[mt][0], al[mt][1], al[mt][2], al[mt][3]);
                }
#pragma unroll
                for (int g = 0; g < 2; g++) {
                    u32 bh0, bh1, bh2, bh3, bl0, bl1, bl2, bl3;
                    ldsm4(bHi + g * (16 * 528) + bo, bh0, bh1, bh2, bh3);
                    ldsm4(bLo + g * (16 * 528) + bo, bl0, bl1, bl2, bl3);
#pragma unroll
                    for (int mt = 0; mt < 2; mt++) {
                        mma16816(acc[mt][2 * g],     ah[mt][0], ah[mt][1], ah[mt][2], ah[mt][3], bh0, bh2);
                        mma16816(acc[mt][2 * g + 1], ah[mt][0], ah[mt][1], ah[mt][2], ah[mt][3], bh1, bh3);
                        mma16816(acc[mt][2 * g],     ah[mt][0], ah[mt][1], ah[mt][2], ah[mt][3], bl0, bl2);
                        mma16816(acc[mt][2 * g + 1], ah[mt][0], ah[mt][1], ah[mt][2], ah[mt][3], bl1, bl3);
                        mma16816(acc[mt][2 * g],     al[mt][0], al[mt][1], al[mt][2], al[mt][3], bh0, bh2);
                        mma16816(acc[mt][2 * g + 1], al[mt][0], al[mt][1], al[mt][2], al[mt][3], bh1, bh3);
                    }
                }
            }
            __syncthreads();
        }

        // epilogue: bias, write fp32 g_out, accumulate BN stats in registers
        const int m0 = wr * 32, n0 = wc * 32;
#pragma unroll
        for (int mt = 0; mt < 2; mt++)
#pragma unroll
            for (int nt = 0; nt < 4; nt++) {
                int col = n0 + nt * 8 + 2 * (lane & 3);
                int r0 = tile * 128 + m0 + mt * 16 + (lane >> 2);
                float bv0 = bias[col], bv1 = bias[col + 1];
                if (r0 < N_NODES) {
                    float o0 = acc[mt][nt][0] + bv0;
                    float o1 = acc[mt][nt][1] + bv1;
                    *(float2*)(g_out + (size_t)r0 * D + col) = make_float2(o0, o1);
                    st_s[nt][0] += o0;  st_s2[nt][0] += o0 * o0;
                    st_s[nt][1] += o1;  st_s2[nt][1] += o1 * o1;
                }
                if (r0 + 8 < N_NODES) {
                    float o0 = acc[mt][nt][2] + bv0;
                    float o1 = acc[mt][nt][3] + bv1;
                    *(float2*)(g_out + (size_t)(r0 + 8) * D + col) = make_float2(o0, o1);
                    st_s[nt][0] += o0;  st_s2[nt][0] += o0 * o0;
                    st_s[nt][1] += o1;  st_s2[nt][1] += o1 * o1;
                }
            }
    }

    // reduce stats across the 8 lane-groups sharing columns (lane stride 4)
#pragma unroll
    for (int nt = 0; nt < 4; nt++)
#pragma unroll
        for (int p = 0; p < 2; p++) {
#pragma unroll
            for (int off = 16; off >= 4; off >>= 1) {
                st_s[nt][p]  += __shfl_xor_sync(0xffffffffu, st_s[nt][p],  off);
                st_s2[nt][p] += __shfl_xor_sync(0xffffffffu, st_s2[nt][p], off);
            }
        }
    if (lane < 4) {
        const int n0 = wc * 32;
#pragma unroll
        for (int nt = 0; nt < 4; nt++) {
            int col = n0 + nt * 8 + 2 * lane;
            atomicAdd(&g_stats[col],           st_s[nt][0]);
            atomicAdd(&g_stats[col + 1],       st_s[nt][1]);
            atomicAdd(&g_stats[128 + col],     st_s2[nt][0]);
            atomicAdd(&g_stats[128 + col + 1], st_s2[nt][1]);
        }
    }
}

// ----------------- BN fold: stats -> per-feature scale/shift, self-reset ----
__global__ void k_bnfold(const float* __restrict__ gamma, const float* __restrict__ beta) {
    int c = threadIdx.x;
    if (c < D) {
        float sum = g_stats[c], sum2 = g_stats[128 + c];
        const float invN = 1.0f / (float)N_NODES;
        float mean = sum * invN;
        float var = sum2 * invN - mean * mean;
        float scl = rsqrtf(var + 1e-5f) * __ldg(gamma + c);
        g_aff[c] = scl;
        g_aff[128 + c] = __ldg(beta + c) - mean * scl;
        g_stats[c] = 0.f;
        g_stats[128 + c] = 0.f;
    }
}

// ----------------- final: apply last BN (no relu) -> d_out ------------------
__global__ void k_final(float* __restrict__ out) {
    int i = blockIdx.x * blockDim.x + threadIdx.x;
    if (i >= N_NODES * 32) return;
    int c0 = (i & 31) * 4;
    float4 v = ((const float4*)g_out)[i];
    float4 sc = *(const float4*)&g_aff[c0];
    float4 sf = *(const float4*)&g_aff[D + c0];
    v.x = fmaf(v.x, sc.x, sf.x);
    v.y = fmaf(v.y, sc.y, sf.y);
    v.z = fmaf(v.z, sc.z, sf.z);
    v.w = fmaf(v.w, sc.w, sf.w);
    ((float4*)out)[i] = v;
}

// ----------------- launch -----------------
extern "C" void kernel_launch(void* const* d_in, const int* in_sizes, int n_in,
                              void* d_out, int out_size) {
    const int*   x    = (const int*)d_in[0];
    const int*   ei   = (const int*)d_in[1];
    const int*   ea   = (const int*)d_in[2];
    const float* elem = (const float*)d_in[3];
    const float* chir = (const float*)d_in[4];
    const float* bt   = (const float*)d_in[5];
    const float* bd   = (const float*)d_in[6];
    const float* W1   = (const float*)d_in[7];
    const float* b1   = (const float*)d_in[8];
    const float* W2   = (const float*)d_in[9];
    const float* b2   = (const float*)d_in[10];
    const float* bng  = (const float*)d_in[11];
    const float* bnb  = (const float*)d_in[12];
    float* out = (float*)d_out;

    static int attr_done = 0;
    if (!attr_done) {
        cudaFuncSetAttribute(kA, cudaFuncAttributeMaxDynamicSharedMemorySize, KA_SMEM);
        cudaFuncSetAttribute(kB, cudaFuncAttributeMaxDynamicSharedMemorySize, KB_SMEM);
        attr_done = 1;
    }

    k_init<<<(N_NODES + 255) / 256, 256>>>(x, bt, bd);
    k_embed<<<(N_NODES * 32 + 255) / 256, 256>>>(x, elem, chir);
    k_hist<<<(N_EDGES + 255) / 256, 256>>>(ei);
    k_scan<<<1, 1024>>>();
    k_fill<<<(N_EDGES + 255) / 256, 256>>>(ei, ea);
    k_prep<<<128, 256>>>(W1, W2);

    for (int l = 0; l < NLAYERS; l++) {
        k_agg<<<(N_NODES + 7) / 8, 256>>>(l);
        kA<<<148, 512, KA_SMEM>>>(b1);
        kB<<<148, 512, KB_SMEM>>>(b2);
        k_bnfold<<<1, 128>>>(bng + l * D, bnb + l * D);
    }
    k_final<<<(N_NODES * 32 + 255) / 256, 256>>>(out);
}